// round 2
// baseline (speedup 1.0000x reference)
#include <cuda_runtime.h>
#include <cstdint>

// Problem constants
#define B_       32
#define S_       160000
#define N_       320
#define H_       160
#define TAU_     257
#define FN_      1000          // (S + H - N)/H + 1
#define LAG_CUT_ 33
#define EPS_     1e-5f
#define OUT_TAUS (TAU_ - LAG_CUT_)   // 224
#define EXT_LEN  (N_ + TAU_ - 1)     // 576

#define WARPS_PER_BLOCK 4
#define SEG_PAD 596   // >= 585 needed by deepest read, multiple of 4 (16B rows)
#define CS_LEN  580   // >= 577, multiple of 4

typedef unsigned long long u64;

// packed f32x2 FMA: both halves independently d = a*b + c
__device__ __forceinline__ u64 fma2(u64 a, u64 b, u64 c) {
    u64 d;
    asm("fma.rn.f32x2 %0, %1, %2, %3;" : "=l"(d) : "l"(a), "l"(b), "l"(c));
    return d;
}
__device__ __forceinline__ float lo32(u64 v) { return __uint_as_float((unsigned)(v & 0xffffffffull)); }
__device__ __forceinline__ float hi32(u64 v) { return __uint_as_float((unsigned)(v >> 32)); }

__global__ void __launch_bounds__(WARPS_PER_BLOCK * 32)
xcorr_kernel(const float* __restrict__ x, float* __restrict__ out) {
    __shared__ __align__(16) float s_seg[WARPS_PER_BLOCK][SEG_PAD];
    __shared__ __align__(16) float s_sh [WARPS_PER_BLOCK][SEG_PAD];
    __shared__ __align__(16) float s_cs [WARPS_PER_BLOCK][CS_LEN];

    const int warp = threadIdx.x >> 5;
    const int lane = threadIdx.x & 31;
    const int w = blockIdx.x * WARPS_PER_BLOCK + warp;   // window id in [0, 32000)
    const int b = w / FN_;
    const int f = w - b * FN_;
    const float* xb = x + (size_t)b * S_;
    const int p  = f * H_;
    const int p2 = (f + 1 == FN_) ? 0 : (f + 1) * H_;    // wraparound frame for f=999

    float* seg = s_seg[warp];
    float* ssh = s_sh[warp];
    float* cs  = s_cs[warp];

    // ---- Phase 1: stage extended window into smem (zero-padded tail) ----
    // seg[j] = xp[p + j]            for j in [0, 320)
    // seg[j] = xp[p2 + (j - 320)]   for j in [320, 576)   (xp pads S.. with zeros)
    for (int j = lane; j < SEG_PAD; j += 32) {
        float v = 0.f;
        if (j < EXT_LEN) {
            int g = (j < N_) ? (p + j) : (p2 + (j - N_));
            if (g < S_) v = xb[g];
        }
        seg[j] = v;
    }
    __syncwarp();

    // shifted copy: ssh[j] = seg[j+1]  -> makes odd-offset pairs 8B-aligned
    for (int j = lane; j < SEG_PAD - 1; j += 32) ssh[j] = seg[j + 1];
    if (lane == 0) ssh[SEG_PAD - 1] = 0.f;

    // ---- Phase 2: warp prefix scan of seg^2 (576 values, 18 per lane) ----
    {
        const int base = lane * 18;
        float partial = 0.f;
        #pragma unroll
        for (int i = 0; i < 18; i++) { float s = seg[base + i]; partial = fmaf(s, s, partial); }
        float incl = partial;
        #pragma unroll
        for (int d = 1; d < 32; d <<= 1) {
            float t = __shfl_up_sync(0xffffffffu, incl, d);
            if (lane >= d) incl += t;
        }
        float run = incl - partial;   // exclusive offset
        #pragma unroll
        for (int i = 0; i < 18; i++) {
            float s = seg[base + i];
            run = fmaf(s, s, run);
            cs[base + i + 1] = run;
        }
        if (lane == 0) cs[0] = 0.f;
    }
    __syncwarp();

    // ---- Phase 3: packed-FMA correlation. Lane owns 8 lags [t_base, t_base+8) ----
    if (lane < 29) {
        const int t_base = 32 + 8 * lane;      // 16B aligned (mod 4 == 0)
        const float* sp = seg + t_base;
        const float* bp = ssh + t_base;

        ulonglong2 A0 = *(const ulonglong2*)(sp);
        ulonglong2 A1 = *(const ulonglong2*)(sp + 4);
        ulonglong2 B0 = *(const ulonglong2*)(bp);
        ulonglong2 B1 = *(const ulonglong2*)(bp + 4);

        u64 acc[8];
        #pragma unroll
        for (int d = 0; d < 8; d++) acc[d] = 0ull;

        #pragma unroll 4
        for (int n = 0; n < N_; n += 4) {
            ulonglong2 A2 = *(const ulonglong2*)(sp + n + 8);
            ulonglong2 B2 = *(const ulonglong2*)(bp + n + 8);
            ulonglong2 K  = *(const ulonglong2*)(seg + n);   // broadcast: kernel taps

            // acc[d] += (k[n],k[n+1]) * (s[m+d],s[m+d+1]) + (k[n+2],k[n+3]) * (s[m+d+2],s[m+d+3])
            acc[0] = fma2(K.x, A0.x, acc[0]); acc[0] = fma2(K.y, A0.y, acc[0]);
            acc[1] = fma2(K.x, B0.x, acc[1]); acc[1] = fma2(K.y, B0.y, acc[1]);
            acc[2] = fma2(K.x, A0.y, acc[2]); acc[2] = fma2(K.y, A1.x, acc[2]);
            acc[3] = fma2(K.x, B0.y, acc[3]); acc[3] = fma2(K.y, B1.x, acc[3]);
            acc[4] = fma2(K.x, A1.x, acc[4]); acc[4] = fma2(K.y, A1.y, acc[4]);
            acc[5] = fma2(K.x, B1.x, acc[5]); acc[5] = fma2(K.y, B1.y, acc[5]);
            acc[6] = fma2(K.x, A1.y, acc[6]); acc[6] = fma2(K.y, A2.x, acc[6]);
            acc[7] = fma2(K.x, B1.y, acc[7]); acc[7] = fma2(K.y, B2.x, acc[7]);

            A0 = A1; A1 = A2;
            B0 = B1; B1 = B2;
        }

        // ---- Epilogue: normalize and store ----
        const float e0 = cs[N_];
        #pragma unroll
        for (int d = 0; d < 8; d++) {
            int tau = t_base + d;
            if (tau >= LAG_CUT_ && tau < TAU_) {
                float num = lo32(acc[d]) + hi32(acc[d]);
                float et  = cs[tau + N_] - cs[tau];
                out[(size_t)w * OUT_TAUS + (tau - LAG_CUT_)] = 2.f * num / (e0 + et + EPS_);
            }
        }
    }
}

extern "C" void kernel_launch(void* const* d_in, const int* in_sizes, int n_in,
                              void* d_out, int out_size) {
    const float* x = (const float*)d_in[0];
    float* out = (float*)d_out;
    const int n_windows = B_ * FN_;                       // 32000
    dim3 grid(n_windows / WARPS_PER_BLOCK);               // 8000 blocks
    xcorr_kernel<<<grid, WARPS_PER_BLOCK * 32>>>(x, out);
}

// round 5
// speedup vs baseline: 1.5476x; 1.5476x over previous
#include <cuda_runtime.h>
#include <cstdint>

// Problem constants
#define B_       32
#define S_       160000
#define N_       320
#define H_       160
#define TAU_     257
#define FN_      1000
#define LAG_CUT_ 33
#define EPS_     1e-5f
#define OUT_TAUS (TAU_ - LAG_CUT_)   // 224
#define EXT_LEN  (N_ + TAU_ - 1)     // 576

#define WARPS_PER_BLOCK 4
#define SEG_PAD 596     // >= 577, multiple of 4
#define CS_LEN  580     // >= 577, multiple of 4
#define KD_LEN  336     // 4 groups of 80 u64 + 4-u64 pad each (332 used)

typedef unsigned long long u64;

__device__ __forceinline__ u64 fma2(u64 a, u64 b, u64 c) {
    u64 d;
    asm("fma.rn.f32x2 %0, %1, %2, %3;" : "=l"(d) : "l"(a), "l"(b), "l"(c));
    return d;
}
__device__ __forceinline__ u64 add2(u64 a, u64 b) {
    u64 d;
    asm("add.rn.f32x2 %0, %1, %2;" : "=l"(d) : "l"(a), "l"(b));
    return d;
}
__device__ __forceinline__ float lo32(u64 v) { return __uint_as_float((unsigned)(v & 0xffffffffull)); }
__device__ __forceinline__ float hi32(u64 v) { return __uint_as_float((unsigned)(v >> 32)); }

__global__ void __launch_bounds__(WARPS_PER_BLOCK * 32, 4)
xcorr_kernel(const float* __restrict__ x, float* __restrict__ out) {
    __shared__ __align__(16) float  s_seg[WARPS_PER_BLOCK][SEG_PAD];
    __shared__ __align__(16) float  s_sh [WARPS_PER_BLOCK][SEG_PAD];
    __shared__ __align__(16) float  s_cs [WARPS_PER_BLOCK][CS_LEN];
    __shared__ __align__(16) float2 s_kd [WARPS_PER_BLOCK][KD_LEN];

    const int warp = threadIdx.x >> 5;
    const int lane = threadIdx.x & 31;
    const int w = blockIdx.x * WARPS_PER_BLOCK + warp;   // window id [0, 32000)
    const int b = w / FN_;
    const int f = w - b * FN_;
    const float* xb = x + (size_t)b * S_;
    const int p  = f * H_;
    const int p2 = (f + 1 == FN_) ? 0 : (f + 1) * H_;    // wrap for f=999

    float*  seg = s_seg[warp];
    float*  ssh = s_sh [warp];
    float*  cs  = s_cs [warp];
    float2* kd  = s_kd [warp];

    // ---- Phase 1: stage extended window (zero-padded tail) ----
    for (int j = lane; j < SEG_PAD; j += 32) {
        float v = 0.f;
        if (j < EXT_LEN) {
            int g = (j < N_) ? (p + j) : (p2 + (j - N_));
            if (g < S_) v = xb[g];
        }
        seg[j] = v;
    }
    __syncwarp();

    // shifted copy: ssh[j] = seg[j+1]
    for (int j = lane; j < SEG_PAD - 1; j += 32) ssh[j] = seg[j + 1];
    if (lane == 0) ssh[SEG_PAD - 1] = 0.f;

    // kdup: duplicated-k pairs, partitioned by tap-group with 32B padding
    // group h (taps [80h, 80h+80)) lives at u64 index [84h, 84h+80)
    for (int n = lane; n < N_; n += 32) {
        float kv = seg[n];
        int grp = n / 80;
        kd[n + 4 * grp] = make_float2(kv, kv);
    }

    // ---- Phase 2: warp prefix scan of seg^2 (576 values) ----
    {
        const int base = lane * 18;
        float partial = 0.f;
        #pragma unroll
        for (int i = 0; i < 18; i++) { float s = seg[base + i]; partial = fmaf(s, s, partial); }
        float incl = partial;
        #pragma unroll
        for (int d = 1; d < 32; d <<= 1) {
            float t = __shfl_up_sync(0xffffffffu, incl, d);
            if (lane >= d) incl += t;
        }
        float run = incl - partial;
        #pragma unroll
        for (int i = 0; i < 18; i++) {
            float s = seg[base + i];
            run = fmaf(s, s, run);
            cs[base + i + 1] = run;
        }
        if (lane == 0) cs[0] = 0.f;
    }
    __syncwarp();

    // ---- Phase 3: 8 lag-groups x 4 tap-groups; 28 lags x 80 taps per lane ----
    const int g = lane & 7;          // lag group
    const int h = lane >> 3;         // tap group
    const int t = LAG_CUT_ + 28 * g; // first lag this lane owns (odd, t-1 % 4 == 0)
    const int start = (t - 1) + 80 * h;  // float index, 16B-aligned

    const float* sp = seg + start;
    const float* bp = ssh + start;
    const float2* kp = kd + 84 * h;

    // sliding windows: 8 chunks of 4 floats each (covers 32 floats)
    ulonglong2 A[8], Bv[8];
    #pragma unroll
    for (int c = 0; c < 7; c++) {
        A[c]  = *(const ulonglong2*)(sp + 4 * c);
        Bv[c] = *(const ulonglong2*)(bp + 4 * c);
    }

    u64 acc[14];
    #pragma unroll
    for (int j = 0; j < 14; j++) acc[j] = 0ull;

    #pragma unroll
    for (int it = 0; it < 20; it++) {
        const int nl = 4 * it;           // local tap base
        A[7]  = *(const ulonglong2*)(sp + nl + 28);
        Bv[7] = *(const ulonglong2*)(bp + nl + 28);
        ulonglong2 kq0 = *(const ulonglong2*)(kp + nl);      // dup(k[n0]), dup(k[n0+1])
        ulonglong2 kq1 = *(const ulonglong2*)(kp + nl + 2);  // dup(k[n0+2]), dup(k[n0+3])

        // tap n0:   pair = ssh u64 at offset 2j      -> Bv[j>>1]   .x/.y by j parity
        #pragma unroll
        for (int j = 0; j < 14; j++)
            acc[j] = fma2(kq0.x, (j & 1) ? Bv[j >> 1].y : Bv[j >> 1].x, acc[j]);
        // tap n0+1: pair = seg u64 at offset 2j+2    -> A[(j+1)>>1] .y if j even, .x if j odd
        #pragma unroll
        for (int j = 0; j < 14; j++)
            acc[j] = fma2(kq0.y, (j & 1) ? A[(j + 1) >> 1].x : A[(j + 1) >> 1].y, acc[j]);
        // tap n0+2: pair = ssh u64 at offset 2j+2
        #pragma unroll
        for (int j = 0; j < 14; j++)
            acc[j] = fma2(kq1.x, (j & 1) ? Bv[(j + 1) >> 1].x : Bv[(j + 1) >> 1].y, acc[j]);
        // tap n0+3: pair = seg u64 at offset 2j+4    -> A[(j+2)>>1] .x if j even, .y if j odd
        #pragma unroll
        for (int j = 0; j < 14; j++)
            acc[j] = fma2(kq1.y, (j & 1) ? A[(j + 2) >> 1].y : A[(j + 2) >> 1].x, acc[j]);

        // slide windows by one chunk
        #pragma unroll
        for (int c = 0; c < 7; c++) { A[c] = A[c + 1]; Bv[c] = Bv[c + 1]; }
    }

    // ---- reduce partial sums across the 4 tap-groups (lane bits 3,4) ----
    #pragma unroll
    for (int j = 0; j < 14; j++) {
        u64 v = acc[j];
        v = add2(v, __shfl_xor_sync(0xffffffffu, v, 8));
        v = add2(v, __shfl_xor_sync(0xffffffffu, v, 16));
        acc[j] = v;
    }

    // ---- Epilogue: normalize + store. tap-group h writes j = h, h+4, h+8, h+12 ----
    const float e0 = cs[N_];
    float* ow = out + (size_t)w * OUT_TAUS + 28 * g;
    #pragma unroll
    for (int j0 = 0; j0 < 4; j0++) {
        int j = h + 4 * j0;
        if (j < 14) {
            int tau = t + 2 * j;
            float n0 = lo32(acc[j]);
            float n1 = hi32(acc[j]);
            float d0 = e0 + (cs[tau + N_]     - cs[tau])     + EPS_;
            float d1 = e0 + (cs[tau + N_ + 1] - cs[tau + 1]) + EPS_;
            float2 r = make_float2(__fdividef(2.f * n0, d0),
                                   __fdividef(2.f * n1, d1));
            *(float2*)(ow + 2 * j) = r;
        }
    }
}

extern "C" void kernel_launch(void* const* d_in, const int* in_sizes, int n_in,
                              void* d_out, int out_size) {
    const float* x = (const float*)d_in[0];
    float* out = (float*)d_out;
    const int n_windows = B_ * FN_;                       // 32000
    dim3 grid(n_windows / WARPS_PER_BLOCK);               // 8000 blocks
    xcorr_kernel<<<grid, WARPS_PER_BLOCK * 32>>>(x, out);
}

// round 6
// speedup vs baseline: 1.6242x; 1.0494x over previous
#include <cuda_runtime.h>
#include <cstdint>

// Problem constants
#define B_       32
#define S_       160000
#define N_       320
#define H_       160
#define TAU_     257
#define FN_      1000
#define LAG_CUT_ 33
#define EPS_     1e-5f
#define OUT_TAUS (TAU_ - LAG_CUT_)   // 224
#define EXT_LEN  (N_ + TAU_ - 1)     // 576

#define WARPS_PER_BLOCK 4
#define SEG_PAD 596     // >= 583 (deepest prefetch read), multiple of 4
#define CS_LEN  580     // >= 577, multiple of 4
#define KD_LEN  336     // 4 groups of 80 u64 + 4-u64 pad each

typedef unsigned long long u64;

__device__ __forceinline__ u64 fma2(u64 a, u64 b, u64 c) {
    u64 d;
    asm("fma.rn.f32x2 %0, %1, %2, %3;" : "=l"(d) : "l"(a), "l"(b), "l"(c));
    return d;
}
__device__ __forceinline__ u64 add2(u64 a, u64 b) {
    u64 d;
    asm("add.rn.f32x2 %0, %1, %2;" : "=l"(d) : "l"(a), "l"(b));
    return d;
}
__device__ __forceinline__ float lo32(u64 v) { return __uint_as_float((unsigned)(v & 0xffffffffull)); }
__device__ __forceinline__ float hi32(u64 v) { return __uint_as_float((unsigned)(v >> 32)); }

__global__ void __launch_bounds__(WARPS_PER_BLOCK * 32, 4)
xcorr_kernel(const float* __restrict__ x, float* __restrict__ out) {
    __shared__ __align__(16) float  s_seg[WARPS_PER_BLOCK][SEG_PAD];
    __shared__ __align__(16) float  s_sh [WARPS_PER_BLOCK][SEG_PAD];
    __shared__ __align__(16) float  s_cs [WARPS_PER_BLOCK][CS_LEN];
    __shared__ __align__(16) float2 s_kd [WARPS_PER_BLOCK][KD_LEN];

    const int warp = threadIdx.x >> 5;
    const int lane = threadIdx.x & 31;
    const int w = blockIdx.x * WARPS_PER_BLOCK + warp;   // window id [0, 32000)
    const int b = w / FN_;
    const int f = w - b * FN_;
    const float* xb = x + (size_t)b * S_;
    const int p  = f * H_;
    const int p2 = (f + 1 == FN_) ? 0 : (f + 1) * H_;    // wrap for f=999

    float*  seg = s_seg[warp];
    float*  ssh = s_sh [warp];
    float*  cs  = s_cs [warp];
    float2* kd  = s_kd [warp];

    // ---- Phase 1: stage extended window (zero-padded tail) ----
    for (int j = lane; j < SEG_PAD; j += 32) {
        float v = 0.f;
        if (j < EXT_LEN) {
            int g = (j < N_) ? (p + j) : (p2 + (j - N_));
            if (g < S_) v = xb[g];
        }
        seg[j] = v;
    }
    __syncwarp();

    // shifted copy: ssh[j] = seg[j+1]
    for (int j = lane; j < SEG_PAD - 1; j += 32) ssh[j] = seg[j + 1];
    if (lane == 0) ssh[SEG_PAD - 1] = 0.f;

    // kdup: duplicated-k pairs, partitioned by tap-group with 32B padding
    // group h (taps [80h, 80h+80)) lives at u64 index [84h, 84h+80); pad zeroed
    for (int n = lane; n < N_; n += 32) {
        float kv = seg[n];
        int grp = n / 80;
        kd[n + 4 * grp] = make_float2(kv, kv);
    }
    if (lane < 16) {                      // zero the 4-u64 pads (safe prefetch targets)
        int grp = lane >> 2;
        kd[80 + 84 * grp + (lane & 3)] = make_float2(0.f, 0.f);
    }

    // ---- Phase 2: warp prefix scan of seg^2 (576 values) ----
    {
        const int base = lane * 18;
        float partial = 0.f;
        #pragma unroll
        for (int i = 0; i < 18; i++) { float s = seg[base + i]; partial = fmaf(s, s, partial); }
        float incl = partial;
        #pragma unroll
        for (int d = 1; d < 32; d <<= 1) {
            float t = __shfl_up_sync(0xffffffffu, incl, d);
            if (lane >= d) incl += t;
        }
        float run = incl - partial;
        #pragma unroll
        for (int i = 0; i < 18; i++) {
            float s = seg[base + i];
            run = fmaf(s, s, run);
            cs[base + i + 1] = run;
        }
        if (lane == 0) cs[0] = 0.f;
    }
    __syncwarp();

    // ---- Phase 3: 8 lag-groups x 4 tap-groups; 28 lags x 80 taps per lane ----
    const int g = lane & 7;          // lag group
    const int h = lane >> 3;         // tap group
    const int t = LAG_CUT_ + 28 * g; // first lag this lane owns
    const int start = (t - 1) + 80 * h;  // float index, 16B-aligned

    const float* sp = seg + start;
    const float* bp = ssh + start;
    const float2* kp = kd + 84 * h;

    // sliding windows: 8 chunks of 4 floats (chunks 0..6 preloaded; 7 = incoming)
    ulonglong2 A[8], Bv[8];
    #pragma unroll
    for (int c = 0; c < 7; c++) {
        A[c]  = *(const ulonglong2*)(sp + 4 * c);
        Bv[c] = *(const ulonglong2*)(bp + 4 * c);
    }

    u64 acc[14];
    #pragma unroll
    for (int j = 0; j < 14; j++) acc[j] = 0ull;

    // software pipeline: prefetch iter-0 incoming chunks + k quads
    ulonglong2 An = *(const ulonglong2*)(sp + 28);
    ulonglong2 Bn = *(const ulonglong2*)(bp + 28);
    ulonglong2 k0 = *(const ulonglong2*)(kp);
    ulonglong2 k1 = *(const ulonglong2*)(kp + 2);

    #pragma unroll
    for (int it = 0; it < 20; it++) {
        A[7]  = An;
        Bv[7] = Bn;
        const ulonglong2 kq0 = k0;
        const ulonglong2 kq1 = k1;

        // prefetch next iteration (unconditional; pads make one-past-end safe)
        An = *(const ulonglong2*)(sp + 4 * it + 32);
        Bn = *(const ulonglong2*)(bp + 4 * it + 32);
        k0 = *(const ulonglong2*)(kp + 4 * it + 4);
        k1 = *(const ulonglong2*)(kp + 4 * it + 6);

        // tap n0:   pair = ssh u64 at offset 2j
        #pragma unroll
        for (int j = 0; j < 14; j++)
            acc[j] = fma2(kq0.x, (j & 1) ? Bv[j >> 1].y : Bv[j >> 1].x, acc[j]);
        // tap n0+1: pair = seg u64 at offset 2j+2
        #pragma unroll
        for (int j = 0; j < 14; j++)
            acc[j] = fma2(kq0.y, (j & 1) ? A[(j + 1) >> 1].x : A[(j + 1) >> 1].y, acc[j]);
        // tap n0+2: pair = ssh u64 at offset 2j+2
        #pragma unroll
        for (int j = 0; j < 14; j++)
            acc[j] = fma2(kq1.x, (j & 1) ? Bv[(j + 1) >> 1].x : Bv[(j + 1) >> 1].y, acc[j]);
        // tap n0+3: pair = seg u64 at offset 2j+4
        #pragma unroll
        for (int j = 0; j < 14; j++)
            acc[j] = fma2(kq1.y, (j & 1) ? A[(j + 2) >> 1].y : A[(j + 2) >> 1].x, acc[j]);

        // slide windows by one chunk (renamed away under full unroll)
        #pragma unroll
        for (int c = 0; c < 7; c++) { A[c] = A[c + 1]; Bv[c] = Bv[c + 1]; }
    }

    // ---- reduce partial sums across the 4 tap-groups (lane bits 3,4) ----
    #pragma unroll
    for (int j = 0; j < 14; j++) {
        u64 v = acc[j];
        v = add2(v, __shfl_xor_sync(0xffffffffu, v, 8));
        v = add2(v, __shfl_xor_sync(0xffffffffu, v, 16));
        acc[j] = v;
    }

    // ---- Epilogue: normalize + store. tap-group h writes j = h, h+4, h+8, h+12 ----
    const float e0 = cs[N_];
    float* ow = out + (size_t)w * OUT_TAUS + 28 * g;
    #pragma unroll
    for (int j0 = 0; j0 < 4; j0++) {
        int j = h + 4 * j0;
        if (j < 14) {
            int tau = t + 2 * j;
            float n0 = lo32(acc[j]);
            float n1 = hi32(acc[j]);
            float d0 = e0 + (cs[tau + N_]     - cs[tau])     + EPS_;
            float d1 = e0 + (cs[tau + N_ + 1] - cs[tau + 1]) + EPS_;
            float2 r = make_float2(__fdividef(2.f * n0, d0),
                                   __fdividef(2.f * n1, d1));
            *(float2*)(ow + 2 * j) = r;
        }
    }
}

extern "C" void kernel_launch(void* const* d_in, const int* in_sizes, int n_in,
                              void* d_out, int out_size) {
    const float* x = (const float*)d_in[0];
    float* out = (float*)d_out;
    const int n_windows = B_ * FN_;                       // 32000
    dim3 grid(n_windows / WARPS_PER_BLOCK);               // 8000 blocks
    xcorr_kernel<<<grid, WARPS_PER_BLOCK * 32>>>(x, out);
}

// round 7
// speedup vs baseline: 1.9568x; 1.2048x over previous
#include <cuda_runtime.h>
#include <cstdint>

// Problem constants
#define B_       32
#define S_       160000
#define N_       320
#define H_       160
#define TAU_     257
#define FN_      1000
#define LAG_CUT_ 33
#define EPS_     1e-5f
#define OUT_TAUS (TAU_ - LAG_CUT_)   // 224
#define EXT_LEN  (N_ + TAU_ - 1)     // 576

#define WARPS_PER_BLOCK 4
#define SEG_PAD 596     // >= 583 (deepest prefetch read), multiple of 4
#define CS_LEN  580     // >= 577, multiple of 4
#define KD_LEN  336     // 4 groups of 80 u64 + 4-u64 pad each

typedef unsigned long long u64;

__device__ __forceinline__ u64 fma2(u64 a, u64 b, u64 c) {
    u64 d;
    asm("fma.rn.f32x2 %0, %1, %2, %3;" : "=l"(d) : "l"(a), "l"(b), "l"(c));
    return d;
}
__device__ __forceinline__ u64 add2(u64 a, u64 b) {
    u64 d;
    asm("add.rn.f32x2 %0, %1, %2;" : "=l"(d) : "l"(a), "l"(b));
    return d;
}
__device__ __forceinline__ float lo32(u64 v) { return __uint_as_float((unsigned)(v & 0xffffffffull)); }
__device__ __forceinline__ float hi32(u64 v) { return __uint_as_float((unsigned)(v >> 32)); }

__global__ void __launch_bounds__(WARPS_PER_BLOCK * 32, 4)
xcorr_kernel(const float* __restrict__ x, float* __restrict__ out) {
    __shared__ __align__(16) float  s_seg[WARPS_PER_BLOCK][SEG_PAD];
    __shared__ __align__(16) float  s_sh [WARPS_PER_BLOCK][SEG_PAD];
    __shared__ __align__(16) float  s_cs [WARPS_PER_BLOCK][CS_LEN];
    __shared__ __align__(16) float2 s_kd [WARPS_PER_BLOCK][KD_LEN];

    const int warp = threadIdx.x >> 5;
    const int lane = threadIdx.x & 31;
    const int w = blockIdx.x * WARPS_PER_BLOCK + warp;   // window id [0, 32000)
    const int b = w / FN_;
    const int f = w - b * FN_;
    const float* xb = x + (size_t)b * S_;
    const int p  = f * H_;
    const int p2 = (f + 1 == FN_) ? 0 : (f + 1) * H_;    // wrap for f=999

    float*  seg = s_seg[warp];
    float*  ssh = s_sh [warp];
    float*  cs  = s_cs [warp];
    float2* kd  = s_kd [warp];

    // ---- Phase 1: stage extended window. BATCHED: all LDGs in flight first
    // (MLP=18), then all STS. A rolled loop serializes at L2 latency. ----
    {
        float v[18];
        #pragma unroll
        for (int i = 0; i < 18; i++) {
            const int j = lane + 32 * i;          // j < 576 always
            const int g = (j < N_) ? (p + j) : (p2 + (j - N_));
            v[i] = (g < S_) ? __ldg(xb + g) : 0.f;
        }
        #pragma unroll
        for (int i = 0; i < 18; i++) seg[lane + 32 * i] = v[i];
        // zero tail [576, 596)
        if (lane < 20) seg[EXT_LEN + lane] = 0.f;
    }
    __syncwarp();

    // ---- shifted copy: ssh[j] = seg[j+1]. Batched LDS then STS. ----
    {
        float v[19];
        #pragma unroll
        for (int i = 0; i < 19; i++) {
            const int j = lane + 32 * i;
            v[i] = (j < SEG_PAD - 1) ? seg[j + 1] : 0.f;
        }
        #pragma unroll
        for (int i = 0; i < 19; i++) {
            const int j = lane + 32 * i;
            if (j < SEG_PAD) ssh[j] = v[i];
        }
    }

    // ---- kdup: duplicated-k pairs, 4 tap-groups, 32B pad each. Batched. ----
    {
        float v[10];
        #pragma unroll
        for (int i = 0; i < 10; i++) v[i] = seg[lane + 32 * i];   // taps 0..319
        #pragma unroll
        for (int i = 0; i < 10; i++) {
            const int n = lane + 32 * i;
            const int grp = n / 80;
            kd[n + 4 * grp] = make_float2(v[i], v[i]);
        }
        if (lane < 16) {                  // zero the pads (safe prefetch targets)
            const int grp = lane >> 2;
            kd[80 + 84 * grp + (lane & 3)] = make_float2(0.f, 0.f);
        }
    }

    // ---- Phase 2: warp prefix scan of seg^2 (576 values) ----
    {
        const int base = lane * 18;
        float sv[18];
        #pragma unroll
        for (int i = 0; i < 18; i++) sv[i] = seg[base + i];
        float partial = 0.f;
        #pragma unroll
        for (int i = 0; i < 18; i++) partial = fmaf(sv[i], sv[i], partial);
        float incl = partial;
        #pragma unroll
        for (int d = 1; d < 32; d <<= 1) {
            float t = __shfl_up_sync(0xffffffffu, incl, d);
            if (lane >= d) incl += t;
        }
        float run = incl - partial;
        #pragma unroll
        for (int i = 0; i < 18; i++) {
            run = fmaf(sv[i], sv[i], run);
            cs[base + i + 1] = run;
        }
        if (lane == 0) cs[0] = 0.f;
    }
    __syncwarp();

    // ---- Phase 3: 8 lag-groups x 4 tap-groups; 28 lags x 80 taps per lane ----
    const int g = lane & 7;          // lag group
    const int h = lane >> 3;         // tap group
    const int t = LAG_CUT_ + 28 * g; // first lag this lane owns
    const int start = (t - 1) + 80 * h;  // float index, 16B-aligned

    const float* sp = seg + start;
    const float* bp = ssh + start;
    const float2* kp = kd + 84 * h;

    // sliding windows: 8 chunks of 4 floats (chunks 0..6 preloaded; 7 = incoming)
    ulonglong2 A[8], Bv[8];
    #pragma unroll
    for (int c = 0; c < 7; c++) {
        A[c]  = *(const ulonglong2*)(sp + 4 * c);
        Bv[c] = *(const ulonglong2*)(bp + 4 * c);
    }

    u64 acc[14];
    #pragma unroll
    for (int j = 0; j < 14; j++) acc[j] = 0ull;

    // software pipeline: prefetch iter-0 incoming chunks + k quads
    ulonglong2 An = *(const ulonglong2*)(sp + 28);
    ulonglong2 Bn = *(const ulonglong2*)(bp + 28);
    ulonglong2 k0 = *(const ulonglong2*)(kp);
    ulonglong2 k1 = *(const ulonglong2*)(kp + 2);

    #pragma unroll
    for (int it = 0; it < 20; it++) {
        A[7]  = An;
        Bv[7] = Bn;
        const ulonglong2 kq0 = k0;
        const ulonglong2 kq1 = k1;

        // prefetch next iteration (unconditional; pads make one-past-end safe)
        An = *(const ulonglong2*)(sp + 4 * it + 32);
        Bn = *(const ulonglong2*)(bp + 4 * it + 32);
        k0 = *(const ulonglong2*)(kp + 4 * it + 4);
        k1 = *(const ulonglong2*)(kp + 4 * it + 6);

        // tap n0:   pair = ssh u64 at offset 2j
        #pragma unroll
        for (int j = 0; j < 14; j++)
            acc[j] = fma2(kq0.x, (j & 1) ? Bv[j >> 1].y : Bv[j >> 1].x, acc[j]);
        // tap n0+1: pair = seg u64 at offset 2j+2
        #pragma unroll
        for (int j = 0; j < 14; j++)
            acc[j] = fma2(kq0.y, (j & 1) ? A[(j + 1) >> 1].x : A[(j + 1) >> 1].y, acc[j]);
        // tap n0+2: pair = ssh u64 at offset 2j+2
        #pragma unroll
        for (int j = 0; j < 14; j++)
            acc[j] = fma2(kq1.x, (j & 1) ? Bv[(j + 1) >> 1].x : Bv[(j + 1) >> 1].y, acc[j]);
        // tap n0+3: pair = seg u64 at offset 2j+4
        #pragma unroll
        for (int j = 0; j < 14; j++)
            acc[j] = fma2(kq1.y, (j & 1) ? A[(j + 2) >> 1].y : A[(j + 2) >> 1].x, acc[j]);

        // slide windows by one chunk (renamed away under full unroll)
        #pragma unroll
        for (int c = 0; c < 7; c++) { A[c] = A[c + 1]; Bv[c] = Bv[c + 1]; }
    }

    // ---- reduce partial sums across the 4 tap-groups (lane bits 3,4) ----
    #pragma unroll
    for (int j = 0; j < 14; j++) {
        u64 v = acc[j];
        v = add2(v, __shfl_xor_sync(0xffffffffu, v, 8));
        v = add2(v, __shfl_xor_sync(0xffffffffu, v, 16));
        acc[j] = v;
    }

    // ---- Epilogue: normalize + store. tap-group h writes j = h, h+4, h+8, h+12 ----
    const float e0 = cs[N_];
    float* ow = out + (size_t)w * OUT_TAUS + 28 * g;
    #pragma unroll
    for (int j0 = 0; j0 < 4; j0++) {
        int j = h + 4 * j0;
        if (j < 14) {
            int tau = t + 2 * j;
            float n0 = lo32(acc[j]);
            float n1 = hi32(acc[j]);
            float d0 = e0 + (cs[tau + N_]     - cs[tau])     + EPS_;
            float d1 = e0 + (cs[tau + N_ + 1] - cs[tau + 1]) + EPS_;
            float2 r = make_float2(__fdividef(2.f * n0, d0),
                                   __fdividef(2.f * n1, d1));
            *(float2*)(ow + 2 * j) = r;
        }
    }
}

extern "C" void kernel_launch(void* const* d_in, const int* in_sizes, int n_in,
                              void* d_out, int out_size) {
    const float* x = (const float*)d_in[0];
    float* out = (float*)d_out;
    const int n_windows = B_ * FN_;                       // 32000
    dim3 grid(n_windows / WARPS_PER_BLOCK);               // 8000 blocks
    xcorr_kernel<<<grid, WARPS_PER_BLOCK * 32>>>(x, out);
}